// round 1
// baseline (speedup 1.0000x reference)
#include <cuda_runtime.h>
#include <math.h>

#define EMB     2048
#define NHEADS  8
#define HDIM    256            // EMB / NHEADS
#define BATCH   2
#define SEQ     2048
#define BH      (BATCH * NHEADS)
#define QKV_N   (3 * EMB)      // 6144

#define BM 128
#define BN 128
#define BK 8
#define TPB 256

// ---------------- scratch (device globals; no allocation allowed) ----------
__device__ float g_Q[(size_t)BH * SEQ * HDIM];     // 32 MB
__device__ float g_K[(size_t)BH * SEQ * HDIM];     // 32 MB
__device__ float g_V[(size_t)BH * SEQ * HDIM];     // 32 MB
__device__ float g_E[(size_t)BH * SEQ * SEQ];      // 256 MB (energy, then att in-place)
__device__ float g_ctx[(size_t)BATCH * SEQ * EMB]; // 32 MB

// ---------------- shared 128x128x8 fp32 GEMM tile ---------------------------
// A is row-major [M, K] with leading dim lda.
// If NT: Bm is row-major [N, K] with leading dim ldb (C = A * B^T).
// Else : Bm is row-major [K, N] with leading dim ldb (C = A * B).
template <bool NT>
__device__ __forceinline__ void gemm_tile(
    const float* __restrict__ A, const float* __restrict__ Bm,
    int lda, int ldb, int K, int bm, int bn, float acc[8][8])
{
    __shared__ float As[BK][BM];
    __shared__ float Bs[BK][BN];
    const int tid = threadIdx.x;
    const int ty = tid >> 4;        // 0..15
    const int tx = tid & 15;        // 0..15

    for (int k0 = 0; k0 < K; k0 += BK) {
        // load A tile (BM x BK), stored transposed
        #pragma unroll
        for (int t = tid; t < BM * BK; t += TPB) {
            int r = t >> 3, c = t & 7;
            As[c][r] = A[(size_t)(bm + r) * lda + (k0 + c)];
        }
        if (NT) {
            #pragma unroll
            for (int t = tid; t < BN * BK; t += TPB) {
                int n = t >> 3, k = t & 7;
                Bs[k][n] = Bm[(size_t)(bn + n) * ldb + (k0 + k)];
            }
        } else {
            #pragma unroll
            for (int t = tid; t < BN * BK; t += TPB) {
                int r = t >> 7, c = t & 127;
                Bs[r][c] = Bm[(size_t)(k0 + r) * ldb + (bn + c)];
            }
        }
        __syncthreads();

        #pragma unroll
        for (int k = 0; k < BK; k++) {
            float ra[8], rb[8];
            #pragma unroll
            for (int i = 0; i < 8; i++) ra[i] = As[k][ty * 8 + i];
            #pragma unroll
            for (int j = 0; j < 8; j++) rb[j] = Bs[k][tx * 8 + j];
            #pragma unroll
            for (int i = 0; i < 8; i++)
                #pragma unroll
                for (int j = 0; j < 8; j++)
                    acc[i][j] = fmaf(ra[i], rb[j], acc[i][j]);
        }
        __syncthreads();
    }
}

// ---------------- 1. QKV GEMM: [4096,2048] x [2048,6144] + bias ------------
// Epilogue de-interleaves column c = h*768 + d*3 + idx into Q/K/V [bh, n, d].
__global__ __launch_bounds__(TPB) void qkv_kernel(
    const float* __restrict__ x, const float* __restrict__ w,
    const float* __restrict__ bias)
{
    const int bm = blockIdx.y * BM, bn = blockIdx.x * BN;
    float acc[8][8] = {};
    gemm_tile<false>(x, w, EMB, QKV_N, EMB, bm, bn, acc);

    const int ty = threadIdx.x >> 4, tx = threadIdx.x & 15;
    #pragma unroll
    for (int i = 0; i < 8; i++) {
        int m = bm + ty * 8 + i;
        int bi = m >> 11;            // m / SEQ
        int ni = m & (SEQ - 1);
        #pragma unroll
        for (int j = 0; j < 8; j++) {
            int c = bn + tx * 8 + j;
            float v = acc[i][j] + bias[c];
            int h   = c / (3 * HDIM);
            int r   = c - h * (3 * HDIM);
            int d   = r / 3;
            int idx = r - d * 3;
            float* dst = (idx == 0) ? g_Q : (idx == 1) ? g_K : g_V;
            dst[((size_t)(bi * NHEADS + h) * SEQ + ni) * HDIM + d] = v;
        }
    }
}

// ---------------- 2. Energy: E = Q * K^T per (b,h) -------------------------
__global__ __launch_bounds__(TPB) void energy_kernel()
{
    const int z = blockIdx.z;
    const float* Qp = g_Q + (size_t)z * SEQ * HDIM;
    const float* Kp = g_K + (size_t)z * SEQ * HDIM;
    float*       Ep = g_E + (size_t)z * SEQ * SEQ;

    const int bm = blockIdx.y * BM, bn = blockIdx.x * BN;
    float acc[8][8] = {};
    gemm_tile<true>(Qp, Kp, HDIM, HDIM, HDIM, bm, bn, acc);

    const int ty = threadIdx.x >> 4, tx = threadIdx.x & 15;
    #pragma unroll
    for (int i = 0; i < 8; i++) {
        int m = bm + ty * 8 + i;
        #pragma unroll
        for (int j = 0; j < 8; j++) {
            int c = bn + tx * 8 + j;
            Ep[(size_t)m * SEQ + c] = acc[i][j];
        }
    }
}

// ---------------- 3. Row softmax (unscaled logits), then /sqrt(EMB) --------
__global__ __launch_bounds__(256) void softmax_kernel()
{
    float* row = g_E + (size_t)blockIdx.x * SEQ;
    const int tid = threadIdx.x;
    __shared__ float red[256];

    float v[8];
    float mx = -INFINITY;
    #pragma unroll
    for (int j = 0; j < 8; j++) {
        v[j] = row[tid + j * 256];
        mx = fmaxf(mx, v[j]);
    }
    red[tid] = mx;
    __syncthreads();
    #pragma unroll
    for (int s = 128; s > 0; s >>= 1) {
        if (tid < s) red[tid] = fmaxf(red[tid], red[tid + s]);
        __syncthreads();
    }
    mx = red[0];
    __syncthreads();

    float sum = 0.f;
    #pragma unroll
    for (int j = 0; j < 8; j++) {
        v[j] = expf(v[j] - mx);
        sum += v[j];
    }
    red[tid] = sum;
    __syncthreads();
    #pragma unroll
    for (int s = 128; s > 0; s >>= 1) {
        if (tid < s) red[tid] += red[tid + s];
        __syncthreads();
    }
    // softmax / sqrt(EMB), sqrt(2048) = 45.254833995939045
    float inv = 1.0f / (red[0] * 45.254833995939045f);
    #pragma unroll
    for (int j = 0; j < 8; j++) row[tid + j * 256] = v[j] * inv;
}

// ---------------- 4. AV: ctx = att * V per (b,h), write [b,n,h*d] ----------
__global__ __launch_bounds__(TPB) void av_kernel()
{
    const int z = blockIdx.z;
    const int bi = z / NHEADS, h = z % NHEADS;
    const float* Ap = g_E + (size_t)z * SEQ * SEQ;
    const float* Vp = g_V + (size_t)z * SEQ * HDIM;

    const int bm = blockIdx.y * BM, bn = blockIdx.x * BN;
    float acc[8][8] = {};
    gemm_tile<false>(Ap, Vp, SEQ, HDIM, SEQ, bm, bn, acc);

    const int ty = threadIdx.x >> 4, tx = threadIdx.x & 15;
    #pragma unroll
    for (int i = 0; i < 8; i++) {
        int m = bm + ty * 8 + i;
        #pragma unroll
        for (int j = 0; j < 8; j++) {
            int d = bn + tx * 8 + j;
            g_ctx[((size_t)(bi * SEQ + m)) * EMB + h * HDIM + d] = acc[i][j];
        }
    }
}

// ---------------- 5. Proj GEMM: out = ctx * w_proj + b_proj ----------------
__global__ __launch_bounds__(TPB) void proj_kernel(
    const float* __restrict__ w, const float* __restrict__ bias,
    float* __restrict__ out)
{
    const int bm = blockIdx.y * BM, bn = blockIdx.x * BN;
    float acc[8][8] = {};
    gemm_tile<false>(g_ctx, w, EMB, EMB, EMB, bm, bn, acc);

    const int ty = threadIdx.x >> 4, tx = threadIdx.x & 15;
    #pragma unroll
    for (int i = 0; i < 8; i++) {
        int m = bm + ty * 8 + i;
        #pragma unroll
        for (int j = 0; j < 8; j++) {
            int c = bn + tx * 8 + j;
            out[(size_t)m * EMB + c] = acc[i][j] + bias[c];
        }
    }
}

// ---------------- launch ----------------------------------------------------
extern "C" void kernel_launch(void* const* d_in, const int* in_sizes, int n_in,
                              void* d_out, int out_size)
{
    (void)in_sizes; (void)n_in; (void)out_size;
    const float* x      = (const float*)d_in[0];
    const float* w_qkv  = (const float*)d_in[1];
    const float* b_qkv  = (const float*)d_in[2];
    const float* w_proj = (const float*)d_in[3];
    const float* b_proj = (const float*)d_in[4];
    float* out = (float*)d_out;

    dim3 blk(TPB);
    qkv_kernel   <<<dim3(QKV_N / BN, (BATCH * SEQ) / BM), blk>>>(x, w_qkv, b_qkv);
    energy_kernel<<<dim3(SEQ / BN, SEQ / BM, BH),          blk>>>();
    softmax_kernel<<<BH * SEQ, 256>>>();
    av_kernel    <<<dim3(HDIM / BN, SEQ / BM, BH),         blk>>>();
    proj_kernel  <<<dim3(EMB / BN, (BATCH * SEQ) / BM),    blk>>>(w_proj, b_proj, out);
}

// round 15
// speedup vs baseline: 2.9779x; 2.9779x over previous
#include <cuda_runtime.h>
#include <cuda_bf16.h>
#include <math.h>
#include <cstdint>

#define EMB     2048
#define NHEADS  8
#define HDIM    256
#define BATCH   2
#define SEQ     2048
#define BH      (BATCH * NHEADS)
#define QKV_N   (3 * EMB)
#define TPB     256

typedef __nv_bfloat16 bf16;

// ===================== scratch (fp32, R1-proven dataflow) ===================
__device__ __align__(256) float g_Q [(size_t)BH * SEQ * HDIM];   // 33.5 MB
__device__ __align__(256) float g_K [(size_t)BH * SEQ * HDIM];   // 33.5 MB
__device__ __align__(256) float g_VT[(size_t)BH * HDIM * SEQ];   // 33.5 MB (V transposed)
__device__ __align__(256) float g_E [(size_t)BH * SEQ * SEQ];    // 268 MB (energy -> att in place)
__device__ __align__(256) float g_ctx[(size_t)BATCH * SEQ * EMB]; // 33.5 MB

// ===================== low-level helpers ====================================
__device__ __forceinline__ void mma16816(float* c, const uint32_t* a,
                                         uint32_t b0, uint32_t b1) {
    asm volatile(
        "mma.sync.aligned.m16n8k16.row.col.f32.bf16.bf16.f32 "
        "{%0,%1,%2,%3}, {%4,%5,%6,%7}, {%8,%9}, {%0,%1,%2,%3};"
        : "+f"(c[0]), "+f"(c[1]), "+f"(c[2]), "+f"(c[3])
        : "r"(a[0]), "r"(a[1]), "r"(a[2]), "r"(a[3]), "r"(b0), "r"(b1));
}
__device__ __forceinline__ void split1(float v, bf16& h, bf16& l) {
    h = __float2bfloat16(v);
    l = __float2bfloat16(v - __bfloat162float(h));
}
__device__ __forceinline__ uint32_t pk(bf16 a, bf16 b) {
    __nv_bfloat162 t = make_bfloat162(a, b);   // .x = a -> low 16 bits
    return reinterpret_cast<uint32_t&>(t);
}

// ===================== GEMM core ============================================
// C[128x128] fp32 regs = A (fp32 row-major [M,K], lda) * B, where
//   BNN=false: B is fp32 row-major [N,K] (ldb)  -> direct row loads
//   BNN=true : B is fp32 row-major [K,N] (ldb)  -> transposed in-load
// Per 32-K chunk: build bf16 hi/lo tiles in smem, accumulate AhBh+AhBl+AlBh.
// smem tile: 128 rows x 32 bf16, rows padded to 40 bf16 (80 B = 20 u32).

__device__ __forceinline__ void fill_rows(const float* __restrict__ S, int ld,
                                          int row0, int k0,
                                          uint32_t* sh, uint32_t* sl) {
    #pragma unroll
    for (int i = 0; i < 4; i++) {
        int idx = threadIdx.x + i * TPB;        // 0..1023
        int r = idx >> 3, q = idx & 7;          // row, float4-slot (k = q*4)
        float4 v = *reinterpret_cast<const float4*>(
            S + (size_t)(row0 + r) * ld + k0 + q * 4);
        bf16 hx, lx, hy, ly, hz, lz, hw, lw;
        split1(v.x, hx, lx); split1(v.y, hy, ly);
        split1(v.z, hz, lz); split1(v.w, hw, lw);
        int o = r * 20 + q * 2;
        sh[o] = pk(hx, hy); sh[o + 1] = pk(hz, hw);
        sl[o] = pk(lx, ly); sl[o + 1] = pk(lz, lw);
    }
}

__device__ __forceinline__ void fill_cols(const float* __restrict__ S, int ld,
                                          int col0, int k0,
                                          uint32_t* shp, uint32_t* slp) {
    bf16* sh = reinterpret_cast<bf16*>(shp);
    bf16* sl = reinterpret_cast<bf16*>(slp);
    #pragma unroll
    for (int i = 0; i < 4; i++) {
        int idx = threadIdx.x + i * TPB;
        int kr = idx & 31, qn = idx >> 5;       // k-row, n-quad
        float4 v = *reinterpret_cast<const float4*>(
            S + (size_t)(k0 + kr) * ld + col0 + qn * 4);
        int n = qn * 4;
        bf16 h, l;
        split1(v.x, h, l); sh[(n + 0) * 40 + kr] = h; sl[(n + 0) * 40 + kr] = l;
        split1(v.y, h, l); sh[(n + 1) * 40 + kr] = h; sl[(n + 1) * 40 + kr] = l;
        split1(v.z, h, l); sh[(n + 2) * 40 + kr] = h; sl[(n + 2) * 40 + kr] = l;
        split1(v.w, h, l); sh[(n + 3) * 40 + kr] = h; sl[(n + 3) * 40 + kr] = l;
    }
}

__device__ __forceinline__ void mma_tiles(const uint32_t* sa, const uint32_t* sb,
                                          float acc[2][8][4],
                                          int wm, int wn, int g, int t) {
    #pragma unroll
    for (int ks = 0; ks < 2; ks++) {
        uint32_t a[2][4];
        #pragma unroll
        for (int mi = 0; mi < 2; mi++) {
            int ra = (wm * 32 + mi * 16 + g) * 20 + ks * 8 + t;
            a[mi][0] = sa[ra];        // rows g,    k 0-7  of chunk half ks
            a[mi][1] = sa[ra + 160];  // rows g+8,  k 0-7
            a[mi][2] = sa[ra + 4];    // rows g,    k 8-15
            a[mi][3] = sa[ra + 164];  // rows g+8,  k 8-15
        }
        #pragma unroll
        for (int nj = 0; nj < 4; nj++) {
            int rb = (wn * 64 + nj * 16 + g) * 20 + ks * 8 + t;
            uint32_t b0 = sb[rb],       b1 = sb[rb + 4];
            uint32_t b2 = sb[rb + 160], b3 = sb[rb + 164];
            mma16816(acc[0][2 * nj],     a[0], b0, b1);
            mma16816(acc[0][2 * nj + 1], a[0], b2, b3);
            mma16816(acc[1][2 * nj],     a[1], b0, b1);
            mma16816(acc[1][2 * nj + 1], a[1], b2, b3);
        }
    }
}

template <bool BNN>
__device__ __forceinline__ void gemm_core(
    const float* __restrict__ A, const float* __restrict__ B,
    int lda, int ldb, int K, int bm, int bn, float acc[2][8][4])
{
    __shared__ __align__(16) uint32_t sAh[2560], sAl[2560];
    __shared__ __align__(16) uint32_t sBh[2560], sBl[2560];

    const int lane = threadIdx.x & 31, wid = threadIdx.x >> 5;
    const int wm = wid & 3, wn = wid >> 2;
    const int g = lane >> 2, t = lane & 3;

    for (int k0 = 0; k0 < K; k0 += 32) {
        fill_rows(A, lda, bm, k0, sAh, sAl);
        if (BNN) fill_cols(B, ldb, bn, k0, sBh, sBl);
        else     fill_rows(B, ldb, bn, k0, sBh, sBl);
        __syncthreads();
        mma_tiles(sAh, sBh, acc, wm, wn, g, t);
        mma_tiles(sAh, sBl, acc, wm, wn, g, t);
        mma_tiles(sAl, sBh, acc, wm, wn, g, t);
        __syncthreads();
    }
}

// Epilogue ownership: for mi{0,1}, h{0,1}, ni 0..7:
//   m = bm + wm*32 + mi*16 + h*8 + (lane>>2)
//   n = bn + wn*64 + ni*8 + (lane&3)*2  (cols n, n+1)
//   values acc[mi][ni][h*2 + {0,1}]
#define EPI_SETUP \
    const int lane = threadIdx.x & 31, wid = threadIdx.x >> 5; \
    const int wm = wid & 3, wn = wid >> 2; \
    const int er = lane >> 2, ec = (lane & 3) * 2;

// ===================== GEMM kernels =========================================
// 1. QKV: x[4096,2048] * w_qkv[2048,6144] + bias -> Q, K (row), V (transposed)
__global__ __launch_bounds__(TPB) void gemm_qkv_kernel(
    const float* __restrict__ x, const float* __restrict__ w,
    const float* __restrict__ bias)
{
    const int bm = blockIdx.y * 128, bn = blockIdx.x * 128;
    float acc[2][8][4] = {};
    gemm_core<true>(x, w, EMB, QKV_N, EMB, bm, bn, acc);
    EPI_SETUP
    #pragma unroll
    for (int mi = 0; mi < 2; mi++)
        #pragma unroll
        for (int h = 0; h < 2; h++) {
            int m = bm + wm * 32 + mi * 16 + h * 8 + er;
            int z0 = (m >> 11) << 3;
            int nn = m & (SEQ - 1);
            #pragma unroll
            for (int ni = 0; ni < 8; ni++) {
                int n = bn + wn * 64 + ni * 8 + ec;
                #pragma unroll
                for (int e = 0; e < 2; e++) {
                    int c = n + e;
                    float v = acc[mi][ni][h * 2 + e] + __ldg(bias + c);
                    int hh = c / 768, r = c - hh * 768, d = r / 3, idx = r - d * 3;
                    int z = z0 + hh;
                    if (idx == 0)
                        g_Q[((size_t)z * SEQ + nn) * HDIM + d] = v;
                    else if (idx == 1)
                        g_K[((size_t)z * SEQ + nn) * HDIM + d] = v;
                    else
                        g_VT[((size_t)z * HDIM + d) * SEQ + nn] = v;
                }
            }
        }
}

// 2. Energy: E[z] = Q[z] * K[z]^T  (M=N=2048, K=256)
__global__ __launch_bounds__(TPB) void gemm_energy_kernel()
{
    const int z = blockIdx.z;
    const size_t zo = (size_t)z * SEQ * HDIM;
    const int bm = blockIdx.y * 128, bn = blockIdx.x * 128;
    float acc[2][8][4] = {};
    gemm_core<false>(g_Q + zo, g_K + zo, HDIM, HDIM, HDIM, bm, bn, acc);
    EPI_SETUP
    float* Ep = g_E + (size_t)z * SEQ * SEQ;
    #pragma unroll
    for (int mi = 0; mi < 2; mi++)
        #pragma unroll
        for (int h = 0; h < 2; h++) {
            int m = bm + wm * 32 + mi * 16 + h * 8 + er;
            #pragma unroll
            for (int ni = 0; ni < 8; ni++) {
                int n = bn + wn * 64 + ni * 8 + ec;
                float2 o = make_float2(acc[mi][ni][h * 2], acc[mi][ni][h * 2 + 1]);
                *reinterpret_cast<float2*>(Ep + (size_t)m * SEQ + n) = o;
            }
        }
}

// 3. row softmax (unscaled logits), then /sqrt(EMB) — R1-proven, in place
__global__ __launch_bounds__(256) void softmax_kernel()
{
    float* row = g_E + (size_t)blockIdx.x * SEQ;
    const int tid = threadIdx.x;
    __shared__ float red[256];

    float v[8];
    float mx = -INFINITY;
    #pragma unroll
    for (int j = 0; j < 8; j++) { v[j] = row[tid + j * 256]; mx = fmaxf(mx, v[j]); }
    red[tid] = mx;
    __syncthreads();
    #pragma unroll
    for (int s = 128; s > 0; s >>= 1) {
        if (tid < s) red[tid] = fmaxf(red[tid], red[tid + s]);
        __syncthreads();
    }
    mx = red[0];
    __syncthreads();
    float sum = 0.f;
    #pragma unroll
    for (int j = 0; j < 8; j++) { v[j] = expf(v[j] - mx); sum += v[j]; }
    red[tid] = sum;
    __syncthreads();
    #pragma unroll
    for (int s = 128; s > 0; s >>= 1) {
        if (tid < s) red[tid] += red[tid + s];
        __syncthreads();
    }
    float inv = 1.0f / (red[0] * 45.254833995939045f);   // /sqrt(2048)
    #pragma unroll
    for (int j = 0; j < 8; j++) row[tid + j * 256] = v[j] * inv;
}

// 4. AV: ctx[z] = att[z] * VT[z]^T  (M=2048, N=256, K=2048) -> [b,n,h*d]
__global__ __launch_bounds__(TPB) void gemm_av_kernel()
{
    const int z = blockIdx.z;
    const int bi = z >> 3, hh = z & 7;
    const int bm = blockIdx.y * 128, bn = blockIdx.x * 128;
    float acc[2][8][4] = {};
    gemm_core<false>(g_E + (size_t)z * SEQ * SEQ, g_VT + (size_t)z * HDIM * SEQ,
                     SEQ, SEQ, SEQ, bm, bn, acc);
    EPI_SETUP
    #pragma unroll
    for (int mi = 0; mi < 2; mi++)
        #pragma unroll
        for (int h = 0; h < 2; h++) {
            int m = bm + wm * 32 + mi * 16 + h * 8 + er;
            size_t base = ((size_t)(bi * SEQ + m)) * EMB + hh * HDIM;
            #pragma unroll
            for (int ni = 0; ni < 8; ni++) {
                int d = bn + wn * 64 + ni * 8 + ec;
                float2 o = make_float2(acc[mi][ni][h * 2], acc[mi][ni][h * 2 + 1]);
                *reinterpret_cast<float2*>(g_ctx + base + d) = o;
            }
        }
}

// 5. proj: out = ctx * w_proj + bias (fp32)
__global__ __launch_bounds__(TPB) void gemm_proj_kernel(
    const float* __restrict__ w, const float* __restrict__ bias,
    float* __restrict__ out)
{
    const int bm = blockIdx.y * 128, bn = blockIdx.x * 128;
    float acc[2][8][4] = {};
    gemm_core<true>(g_ctx, w, EMB, EMB, EMB, bm, bn, acc);
    EPI_SETUP
    #pragma unroll
    for (int mi = 0; mi < 2; mi++)
        #pragma unroll
        for (int h = 0; h < 2; h++) {
            int m = bm + wm * 32 + mi * 16 + h * 8 + er;
            #pragma unroll
            for (int ni = 0; ni < 8; ni++) {
                int n = bn + wn * 64 + ni * 8 + ec;
                float2 o = make_float2(acc[mi][ni][h * 2]     + __ldg(bias + n),
                                       acc[mi][ni][h * 2 + 1] + __ldg(bias + n + 1));
                *reinterpret_cast<float2*>(out + (size_t)m * EMB + n) = o;
            }
        }
}

// ===================== launch ===============================================
extern "C" void kernel_launch(void* const* d_in, const int* in_sizes, int n_in,
                              void* d_out, int out_size)
{
    (void)in_sizes; (void)n_in; (void)out_size;
    const float* x      = (const float*)d_in[0];
    const float* w_qkv  = (const float*)d_in[1];
    const float* b_qkv  = (const float*)d_in[2];
    const float* w_proj = (const float*)d_in[3];
    const float* b_proj = (const float*)d_in[4];
    float* out = (float*)d_out;

    gemm_qkv_kernel   <<<dim3(QKV_N / 128, (BATCH * SEQ) / 128), TPB>>>(x, w_qkv, b_qkv);
    gemm_energy_kernel<<<dim3(SEQ / 128, SEQ / 128, BH),          TPB>>>();
    softmax_kernel    <<<BH * SEQ, 256>>>();
    gemm_av_kernel    <<<dim3(HDIM / 128, SEQ / 128, BH),         TPB>>>();
    gemm_proj_kernel  <<<dim3(EMB / 128, (BATCH * SEQ) / 128),    TPB>>>(w_proj, b_proj, out);
}